// round 4
// baseline (speedup 1.0000x reference)
#include <cuda_runtime.h>

// TSModel: 2-layer LSTM recurrence.
//   layer0: LSTMCell(1, 64); layer1: LSTMCell(64, 1)
//   NOTE: layer1 input is c0 (cell state), per-step output is c1.
// B=2048 rows, T=1024 steps, fp32. Persistent-RNN style:
//   - 293 CTAs x 256 threads, M=7 batch rows per CTA (rows independent -> CTA-local recurrence)
//   - each thread owns one gate row of W_hh0 (64 weights) in registers, packed as 32 f32x2
//   - h broadcast from SMEM (LDS.128), gates via fma.rn.f32x2 (2 MAC/instr)
//   - activations: MUFU.EX2 + RCP.approx (exact sigmoid/tanh identities, err ~1e-6)

#define BATCH 2048
#define TSTEPS 1024
#define UNITS 64
#define GATES 256
#define MROWS 7
#define NCTA ((BATCH + MROWS - 1) / MROWS)   // 293
#define NTHR 256

typedef unsigned long long u64;

__device__ __forceinline__ u64 pack2(float lo, float hi) {
    u64 r;
    asm("mov.b64 %0, {%1, %2};" : "=l"(r) : "f"(lo), "f"(hi));
    return r;
}
__device__ __forceinline__ void unpack2(u64 v, float& lo, float& hi) {
    asm("mov.b64 {%0, %1}, %2;" : "=f"(lo), "=f"(hi) : "l"(v));
}
__device__ __forceinline__ u64 fma2(u64 a, u64 b, u64 c) {
    u64 d;
    asm("fma.rn.f32x2 %0, %1, %2, %3;" : "=l"(d) : "l"(a), "l"(b), "l"(c));
    return d;
}
__device__ __forceinline__ float rcp_apx(float x) {
    float r;
    asm("rcp.approx.f32 %0, %1;" : "=f"(r) : "f"(x));
    return r;
}
// sigmoid(x) = 1 / (1 + e^-x)
__device__ __forceinline__ float sig_f(float x) {
    return rcp_apx(1.0f + __expf(-x));
}
// tanh(x) = 1 - 2/(1 + e^{2x})
__device__ __forceinline__ float tanh_f(float x) {
    return fmaf(-2.0f, rcp_apx(1.0f + __expf(x + x)), 1.0f);
}

__global__ void __launch_bounds__(NTHR, 2)
lstm_kernel(const float* __restrict__ in,
            const float* __restrict__ Wih0, const float* __restrict__ Whh0,
            const float* __restrict__ bih0, const float* __restrict__ bhh0,
            const float* __restrict__ Wih1, const float* __restrict__ Whh1,
            const float* __restrict__ bih1, const float* __restrict__ bhh1,
            float* __restrict__ out) {
    __shared__ __align__(16) float Hs[MROWS][UNITS];
    __shared__ __align__(16) float Cs[MROWS][UNITS];
    __shared__ __align__(16) float Gs[MROWS][GATES];
    __shared__ __align__(16) float Xs[MROWS][TSTEPS];

    const int tid = threadIdx.x;
    const int r0 = blockIdx.x * MROWS;
    const int mrows = min(MROWS, BATCH - r0);

    // ---- one-time setup ----
    // Layer-0 weights: thread tid owns gate row tid (i:0-63, f:64-127, g:128-191, o:192-255)
    u64 w[32];
    {
        const float2* wr = (const float2*)(Whh0 + tid * UNITS);
#pragma unroll
        for (int k = 0; k < 32; k++) {
            float2 v = wr[k];
            w[k] = pack2(v.x, v.y);
        }
    }
    const float wx = Wih0[tid];               // W_ih0 is (256,1)
    const float bsum = bih0[tid] + bhh0[tid];

    const int lane = tid & 31;
    const int wid = tid >> 5;
    // Layer-1: lane l handles gate (l&3), slot (l>>2)
    const int g1 = lane & 3;
    const int s1 = lane >> 2;
    float wi1[8];
#pragma unroll
    for (int k = 0; k < 8; k++) wi1[k] = Wih1[g1 * UNITS + s1 + 8 * k];
    const float whh1g = Whh1[g1];             // W_hh1 is (4,1)
    const float b1g = bih1[g1] + bhh1[g1];

    // Stage input rows into SMEM (contiguous copy, coalesced)
    {
        const float4* src = (const float4*)(in + (size_t)r0 * TSTEPS);
        float4* dst = (float4*)&Xs[0][0];
        const int n4 = mrows * (TSTEPS / 4);
        for (int i = tid; i < n4; i += NTHR) dst[i] = src[i];
    }
    // Zero recurrent state
    for (int i = tid; i < MROWS * UNITS; i += NTHR) {
        (&Hs[0][0])[i] = 0.0f;
        (&Cs[0][0])[i] = 0.0f;
    }
    float h1 = 0.0f, c1 = 0.0f;               // layer-1 state, replicated per lane
    __syncthreads();

    // ---- time loop ----
    for (int t = 0; t < TSTEPS; t++) {
        // Phase A: gates[m][tid] = x*wx + b + dot(W_row, h[m])  (f32x2 packed)
        for (int m = 0; m < mrows; m++) {
            const float xv = Xs[m][t];
            u64 acc0 = pack2(fmaf(xv, wx, bsum), 0.0f);
            u64 acc1 = 0ULL;
            const ulonglong2* hp = (const ulonglong2*)&Hs[m][0];
#pragma unroll
            for (int j = 0; j < 16; j++) {
                ulonglong2 hv = hp[j];        // LDS.128 broadcast
                acc0 = fma2(w[2 * j], hv.x, acc0);
                acc1 = fma2(w[2 * j + 1], hv.y, acc1);
            }
            float a, b, c, d;
            unpack2(acc0, a, b);
            unpack2(acc1, c, d);
            Gs[m][tid] = (a + b) + (c + d);
        }
        __syncthreads();

        // Phase B: per-unit activation + state update (tasks = mrows*64)
#pragma unroll
        for (int k = 0; k < 2; k++) {
            const int task = tid + k * NTHR;
            if (task < mrows * UNITS) {
                const int m = task >> 6;
                const int u = task & 63;
                const float gi = Gs[m][u];
                const float gf = Gs[m][u + 64];
                const float gg = Gs[m][u + 128];
                const float go = Gs[m][u + 192];
                const float cc = Cs[m][u];
                const float cn = sig_f(gf) * cc + sig_f(gi) * tanh_f(gg);
                const float hn = sig_f(go) * tanh_f(cn);
                Cs[m][u] = cn;
                Hs[m][u] = hn;
            }
        }
        __syncthreads();

        // Phase C: layer-1 (input = c0). Warp w owns batch row w.
        if (wid < mrows) {
            const int m = wid;
            float acc = 0.0f;
#pragma unroll
            for (int k = 0; k < 8; k++)
                acc = fmaf(wi1[k], Cs[m][s1 + 8 * k], acc);
            acc += __shfl_xor_sync(0xffffffffu, acc, 4);
            acc += __shfl_xor_sync(0xffffffffu, acc, 8);
            acc += __shfl_xor_sync(0xffffffffu, acc, 16);
            acc += fmaf(whh1g, h1, b1g);      // per-gate bias + recurrent term
            const float gi = __shfl_sync(0xffffffffu, acc, 0);
            const float gf = __shfl_sync(0xffffffffu, acc, 1);
            const float gg = __shfl_sync(0xffffffffu, acc, 2);
            const float go = __shfl_sync(0xffffffffu, acc, 3);
            c1 = sig_f(gf) * c1 + sig_f(gi) * tanh_f(gg);
            h1 = sig_f(go) * tanh_f(c1);
            if (lane == 0) out[(size_t)(r0 + m) * TSTEPS + t] = c1;
        }
        // no sync needed here: next Phase A touches only Hs/Xs/Gs, all ordered
        // by the barrier after Phase B (Gs rewrite races are excluded because
        // every thread finished its Phase-B Gs reads before that barrier).
    }
}

extern "C" void kernel_launch(void* const* d_in, const int* in_sizes, int n_in,
                              void* d_out, int out_size) {
    (void)in_sizes; (void)n_in; (void)out_size;
    lstm_kernel<<<NCTA, NTHR>>>(
        (const float*)d_in[0],  // input (2048,1024)
        (const float*)d_in[1],  // W_ih0 (256,1)
        (const float*)d_in[2],  // W_hh0 (256,64)
        (const float*)d_in[3],  // b_ih0 (256)
        (const float*)d_in[4],  // b_hh0 (256)
        (const float*)d_in[5],  // W_ih1 (4,64)
        (const float*)d_in[6],  // W_hh1 (4,1)
        (const float*)d_in[7],  // b_ih1 (4)
        (const float*)d_in[8],  // b_hh1 (4)
        (float*)d_out);         // out (2048,1024)
}